// round 16
// baseline (speedup 1.0000x reference)
#include <cuda_runtime.h>
#include <cuda_bf16.h>
#include <cstdint>

#define NHID   256
#define NVIS   65536
#define POP    1024
#define TILE_N 256
#define THREADS 256
#define G_ROWS  64                 // rows per group A slice
#define G_TILES 8                  // sub-tiles per group band (512 rows)
#define LOG2E  1.4426950408889634f

// bf16 scratch for hidden only (static device global — allocation-free)
__device__ __nv_bfloat16 g_hidden[(size_t)POP * NHID]; // 512 KB

// SMEM layout (bytes). Rows are 256 bf16 = 512B, xor-swizzled in 16B chunks.
#define SMEM_AVEC 0
#define SMEM_A    1024                        // 2 group slices x 32768
#define SMEM_B    (1024 + 2 * G_ROWS * 512)   // 66560
#define SMEM_TOTAL (SMEM_B + TILE_N * 512)    // 197632

static __device__ __forceinline__ uint32_t smem_u32(const void* p) {
    uint32_t a;
    asm("{ .reg .u64 t; cvta.to.shared.u64 t, %1; cvt.u32.u64 %0, t; }" : "=r"(a) : "l"(p));
    return a;
}

static __device__ __forceinline__ float ex2f(float x) {
    float y;
    asm("ex2.approx.ftz.f32 %0, %1;" : "=f"(y) : "f"(x));
    return y;
}

static __device__ __forceinline__ void cp_async16(uint32_t dst, const void* src) {
    asm volatile("cp.async.cg.shared.global [%0], [%1], 16;" :: "r"(dst), "l"(src) : "memory");
}
static __device__ __forceinline__ void cp_commit() {
    asm volatile("cp.async.commit_group;" ::: "memory");
}
static __device__ __forceinline__ void cp_wait0() {
    asm volatile("cp.async.wait_group 0;" ::: "memory");
}
static __device__ __forceinline__ void gbar(int id) {
    asm volatile("bar.sync %0, %1;" :: "r"(id), "r"(128) : "memory");
}

static __device__ __forceinline__ void ldmat4(uint32_t* r, uint32_t addr) {
    asm volatile("ldmatrix.sync.aligned.m8n8.x4.shared.b16 {%0,%1,%2,%3}, [%4];"
                 : "=r"(r[0]), "=r"(r[1]), "=r"(r[2]), "=r"(r[3]) : "r"(addr));
}

static __device__ __forceinline__ void mma_bf16(float* d, const uint32_t* a, const uint32_t* b) {
    asm volatile(
        "mma.sync.aligned.m16n8k16.row.col.f32.bf16.bf16.f32 "
        "{%0,%1,%2,%3}, {%4,%5,%6,%7}, {%8,%9}, {%0,%1,%2,%3};"
        : "+f"(d[0]), "+f"(d[1]), "+f"(d[2]), "+f"(d[3])
        : "r"(a[0]), "r"(a[1]), "r"(a[2]), "r"(a[3]), "r"(b[0]), "r"(b[1]));
}

// Prologue (tiny): f32 -> bf16 for hidden only.
__global__ void __launch_bounds__(256, 8)
convert_hidden(const float* __restrict__ hidden) {
    size_t t = (size_t)blockIdx.x * blockDim.x + threadIdx.x;
    const size_t hTasks = (size_t)POP * NHID / 8;          // 32,768
    if (t < hTasks) {
        const float4* p = reinterpret_cast<const float4*>(hidden + t * 8);
        float4 x0 = p[0], x1 = p[1];
        union { __nv_bfloat162 h[4]; uint4 u; } pk;
        pk.h[0] = __floats2bfloat162_rn(x0.x, x0.y);
        pk.h[1] = __floats2bfloat162_rn(x0.z, x0.w);
        pk.h[2] = __floats2bfloat162_rn(x1.x, x1.y);
        pk.h[3] = __floats2bfloat162_rn(x1.z, x1.w);
        reinterpret_cast<uint4*>(g_hidden)[t] = pk.u;
    }
}

// One-time per CTA: f32 W tile [TILE_N,256] -> bf16*LOG2E, swizzled smem.
static __device__ __forceinline__ void fill_B_cvt(char* smem,
                                                  const float* __restrict__ src,
                                                  int tid) {
    #pragma unroll
    for (int it = 0; it < TILE_N * 32 / THREADS; it++) {   // 32 iters
        int t  = tid + it * THREADS;
        int r  = t >> 5;
        int kc = (t & 31) << 3;
        const float4* p = reinterpret_cast<const float4*>(src + (size_t)r * NHID + kc);
        float4 x0 = p[0], x1 = p[1];
        union { __nv_bfloat162 h[4]; uint4 u; } pk;
        pk.h[0] = __floats2bfloat162_rn(x0.x * LOG2E, x0.y * LOG2E);
        pk.h[1] = __floats2bfloat162_rn(x0.z * LOG2E, x0.w * LOG2E);
        pk.h[2] = __floats2bfloat162_rn(x1.x * LOG2E, x1.y * LOG2E);
        pk.h[3] = __floats2bfloat162_rn(x1.z * LOG2E, x1.w * LOG2E);
        int chunk = (kc >> 3) ^ (r & 7);
        *reinterpret_cast<uint4*>(smem + SMEM_B + r * 512 + chunk * 16) = pk.u;
    }
}

// Group-scoped: async-copy a 64-row bf16 slice into the group's swizzled A slab.
// 2048 chunks of 16B over 128 threads = 16 per thread.
static __device__ __forceinline__ void fill_slice(uint32_t dst,
                                                  const __nv_bfloat16* __restrict__ src,
                                                  int gtid) {
    #pragma unroll
    for (int it = 0; it < 16; it++) {
        int t = gtid + it * 128;
        int r = t >> 5;
        int c = t & 31;
        int chunk = c ^ (r & 7);
        cp_async16(dst + r * 512 + chunk * 16,
                   src + (size_t)r * NHID + c * 8);
    }
}

__global__ void __launch_bounds__(THREADS, 1)
rbm_softmax_kernel(const float* __restrict__ W, const float* __restrict__ a,
                   float* __restrict__ out) {
    extern __shared__ char smem[];
    const int tid    = threadIdx.x;
    const int lane   = tid & 31;
    const int wid    = tid >> 5;
    const int grp    = wid >> 2;      // 2 groups of 4 consecutive warps (span SMSPs)
    const int gtid   = tid & 127;
    const int warp_n = wid & 3;
    const int cn     = warp_n * 64;
    const int n0     = blockIdx.x * TILE_N;
    const uint32_t sb = smem_u32(smem);
    const uint32_t aSlice = sb + SMEM_A + grp * (G_ROWS * 512);
    const __nv_bfloat16* hband = g_hidden + (size_t)grp * 512 * NHID;

    // Group's first A slice in flight while we convert B.
    fill_slice(aSlice, hband, gtid);
    cp_commit();

    // B tile (W slice, once per CTA): LDG f32 + cvt(*LOG2E) + STS.
    fill_B_cvt(smem, W + (size_t)n0 * NHID, tid);

    float* avec = reinterpret_cast<float*>(smem + SMEM_AVEC);
    if (tid < TILE_N) avec[tid] = a[n0 + tid] * LOG2E;

    // Folded ldmatrix bases: addr(ks) = baseX ^ ((2ks)<<4)  (rows 512B-aligned).
    const int khalf = lane >> 4;
    uint32_t aX[4];
    #pragma unroll
    for (int mi = 0; mi < 4; mi++) {
        int r = mi * 16 + (lane & 15);
        aX[mi] = (aSlice + r * 512) | ((uint32_t)((khalf ^ (r & 7)) << 4));
    }
    uint32_t bXr[4];
    #pragma unroll
    for (int p = 0; p < 4; p++) {
        int r = cn + p * 16 + (lane & 15);
        bXr[p] = (sb + SMEM_B + r * 512) | ((uint32_t)((khalf ^ (r & 7)) << 4));
    }

    cp_wait0();
    __syncthreads();   // B + both groups' slice 0 + avec visible; groups go free after this

    // Hoisted (pre-scaled) bias values for this thread's accumulator columns.
    float av[8][2];
    #pragma unroll
    for (int ni = 0; ni < 8; ni++) {
        int c = cn + ni * 8 + 2 * (lane & 3);
        av[ni][0] = avec[c];
        av[ni][1] = avec[c + 1];
    }

    for (int sub = 0; sub < G_TILES; sub++) {
        float acc[4][8][4];
        #pragma unroll
        for (int mi = 0; mi < 4; mi++)
            #pragma unroll
            for (int ni = 0; ni < 8; ni++)
                #pragma unroll
                for (int j = 0; j < 4; j++) acc[mi][ni][j] = 0.f;

        #pragma unroll 4
        for (int ks = 0; ks < 16; ks++) {
            const uint32_t kx = (uint32_t)((2 * ks) << 4);
            uint32_t af[4][4];
            #pragma unroll
            for (int mi = 0; mi < 4; mi++)
                ldmat4(af[mi], aX[mi] ^ kx);
            uint32_t bf[8][2];
            #pragma unroll
            for (int p = 0; p < 4; p++) {
                uint32_t r4[4];
                ldmat4(r4, bXr[p] ^ kx);
                bf[2 * p][0]     = r4[0];
                bf[2 * p][1]     = r4[2];
                bf[2 * p + 1][0] = r4[1];
                bf[2 * p + 1][1] = r4[3];
            }
            #pragma unroll
            for (int mi = 0; mi < 4; mi++)
                #pragma unroll
                for (int ni = 0; ni < 8; ni++)
                    mma_bf16(acc[mi][ni], af[mi], bf[ni]);
        }
        gbar(1 + grp);     // group done reading its A slice

        // Refill group's A slice for next sub-tile; hides under the epilogue.
        if (sub + 1 < G_TILES) {
            fill_slice(aSlice, hband + (size_t)(sub + 1) * G_ROWS * NHID, gtid);
            cp_commit();
        }

        // Epilogue: per 16-col group, softmax across the 4-lane quad.
        // Logits pre-scaled by log2e -> plain ex2; tiny |logit|: no max-sub.
        const size_t rbase = (size_t)grp * 512 + (size_t)sub * G_ROWS + (lane >> 2);
        const int    cb    = n0 + cn + 2 * (lane & 3);
        #pragma unroll
        for (int mi = 0; mi < 4; mi++) {
            #pragma unroll
            for (int g = 0; g < 4; g++) {
                float e[8];
                e[0] = ex2f(acc[mi][2 * g][0]     + av[2 * g][0]);
                e[1] = ex2f(acc[mi][2 * g][1]     + av[2 * g][1]);
                e[2] = ex2f(acc[mi][2 * g + 1][0] + av[2 * g + 1][0]);
                e[3] = ex2f(acc[mi][2 * g + 1][1] + av[2 * g + 1][1]);
                e[4] = ex2f(acc[mi][2 * g][2]     + av[2 * g][0]);
                e[5] = ex2f(acc[mi][2 * g][3]     + av[2 * g][1]);
                e[6] = ex2f(acc[mi][2 * g + 1][2] + av[2 * g + 1][0]);
                e[7] = ex2f(acc[mi][2 * g + 1][3] + av[2 * g + 1][1]);

                float sA = (e[0] + e[1]) + (e[2] + e[3]);
                float sB = (e[4] + e[5]) + (e[6] + e[7]);
                sA += __shfl_xor_sync(0xffffffffu, sA, 1);
                sB += __shfl_xor_sync(0xffffffffu, sB, 1);
                sA += __shfl_xor_sync(0xffffffffu, sA, 2);
                sB += __shfl_xor_sync(0xffffffffu, sB, 2);
                float iA = __fdividef(1.0f, sA);
                float iB = __fdividef(1.0f, sB);

                size_t row = rbase + (size_t)mi * 16;
                float* o0 = out + row * NVIS + cb + 16 * g;
                *reinterpret_cast<float2*>(o0)     = make_float2(e[0] * iA, e[1] * iA);
                *reinterpret_cast<float2*>(o0 + 8) = make_float2(e[2] * iA, e[3] * iA);
                float* o1 = o0 + (size_t)8 * NVIS;
                *reinterpret_cast<float2*>(o1)     = make_float2(e[4] * iB, e[5] * iB);
                *reinterpret_cast<float2*>(o1 + 8) = make_float2(e[6] * iB, e[7] * iB);
            }
        }

        cp_wait0();
        gbar(1 + grp);     // group's next A slice resident
    }
}

extern "C" void kernel_launch(void* const* d_in, const int* in_sizes, int n_in,
                              void* d_out, int out_size) {
    const float* hidden = (const float*)d_in[0];
    const float* W      = (const float*)d_in[1];
    const float* a      = (const float*)d_in[2];
    float* out          = (float*)d_out;

    convert_hidden<<<(POP * NHID / 8 + 255) / 256, 256>>>(hidden);

    cudaFuncSetAttribute(rbm_softmax_kernel,
                         cudaFuncAttributeMaxDynamicSharedMemorySize, SMEM_TOTAL);
    rbm_softmax_kernel<<<NVIS / TILE_N, THREADS, SMEM_TOTAL>>>(W, a, out);
}

// round 17
// speedup vs baseline: 1.1250x; 1.1250x over previous
#include <cuda_runtime.h>
#include <cuda_bf16.h>
#include <cstdint>

#define NHID   256
#define NVIS   65536
#define POP    1024
#define TILE_N 256
#define THREADS 512
#define G_ROWS  32                 // rows per group A slice
#define G_TILES 8                  // sub-tiles per group band (256 rows)
#define LOG2E  1.4426950408889634f
#define STAGGER_CYC 3000ull        // one-time inter-group skew

// bf16 scratch for hidden only (static device global — allocation-free)
__device__ __nv_bfloat16 g_hidden[(size_t)POP * NHID]; // 512 KB

// SMEM layout (bytes). Rows are 256 bf16 = 512B, xor-swizzled in 16B chunks.
#define SMEM_AVEC 0
#define SMEM_A    1024                        // 4 group slices x 16384
#define SMEM_B    (1024 + 4 * G_ROWS * 512)   // 66560
#define SMEM_TOTAL (SMEM_B + TILE_N * 512)    // 197632

static __device__ __forceinline__ uint32_t smem_u32(const void* p) {
    uint32_t a;
    asm("{ .reg .u64 t; cvta.to.shared.u64 t, %1; cvt.u32.u64 %0, t; }" : "=r"(a) : "l"(p));
    return a;
}

static __device__ __forceinline__ float ex2f(float x) {
    float y;
    asm("ex2.approx.ftz.f32 %0, %1;" : "=f"(y) : "f"(x));
    return y;
}

static __device__ __forceinline__ void cp_async16(uint32_t dst, const void* src) {
    asm volatile("cp.async.cg.shared.global [%0], [%1], 16;" :: "r"(dst), "l"(src) : "memory");
}
static __device__ __forceinline__ void cp_commit() {
    asm volatile("cp.async.commit_group;" ::: "memory");
}
static __device__ __forceinline__ void cp_wait0() {
    asm volatile("cp.async.wait_group 0;" ::: "memory");
}
static __device__ __forceinline__ void gbar(int id) {
    asm volatile("bar.sync %0, %1;" :: "r"(id), "r"(128) : "memory");
}

static __device__ __forceinline__ void ldmat4(uint32_t* r, uint32_t addr) {
    asm volatile("ldmatrix.sync.aligned.m8n8.x4.shared.b16 {%0,%1,%2,%3}, [%4];"
                 : "=r"(r[0]), "=r"(r[1]), "=r"(r[2]), "=r"(r[3]) : "r"(addr));
}

static __device__ __forceinline__ void mma_bf16(float* d, const uint32_t* a, const uint32_t* b) {
    asm volatile(
        "mma.sync.aligned.m16n8k16.row.col.f32.bf16.bf16.f32 "
        "{%0,%1,%2,%3}, {%4,%5,%6,%7}, {%8,%9}, {%0,%1,%2,%3};"
        : "+f"(d[0]), "+f"(d[1]), "+f"(d[2]), "+f"(d[3])
        : "r"(a[0]), "r"(a[1]), "r"(a[2]), "r"(a[3]), "r"(b[0]), "r"(b[1]));
}

// Prologue (tiny): f32 -> bf16 for hidden only.
__global__ void __launch_bounds__(256, 8)
convert_hidden(const float* __restrict__ hidden) {
    size_t t = (size_t)blockIdx.x * blockDim.x + threadIdx.x;
    const size_t hTasks = (size_t)POP * NHID / 8;          // 32,768
    if (t < hTasks) {
        const float4* p = reinterpret_cast<const float4*>(hidden + t * 8);
        float4 x0 = p[0], x1 = p[1];
        union { __nv_bfloat162 h[4]; uint4 u; } pk;
        pk.h[0] = __floats2bfloat162_rn(x0.x, x0.y);
        pk.h[1] = __floats2bfloat162_rn(x0.z, x0.w);
        pk.h[2] = __floats2bfloat162_rn(x1.x, x1.y);
        pk.h[3] = __floats2bfloat162_rn(x1.z, x1.w);
        reinterpret_cast<uint4*>(g_hidden)[t] = pk.u;
    }
}

// One-time per CTA: f32 W tile [TILE_N,256] -> bf16*LOG2E, swizzled smem.
static __device__ __forceinline__ void fill_B_cvt(char* smem,
                                                  const float* __restrict__ src,
                                                  int tid) {
    #pragma unroll
    for (int it = 0; it < TILE_N * 32 / THREADS; it++) {   // 16 iters
        int t  = tid + it * THREADS;
        int r  = t >> 5;
        int kc = (t & 31) << 3;
        const float4* p = reinterpret_cast<const float4*>(src + (size_t)r * NHID + kc);
        float4 x0 = p[0], x1 = p[1];
        union { __nv_bfloat162 h[4]; uint4 u; } pk;
        pk.h[0] = __floats2bfloat162_rn(x0.x * LOG2E, x0.y * LOG2E);
        pk.h[1] = __floats2bfloat162_rn(x0.z * LOG2E, x0.w * LOG2E);
        pk.h[2] = __floats2bfloat162_rn(x1.x * LOG2E, x1.y * LOG2E);
        pk.h[3] = __floats2bfloat162_rn(x1.z * LOG2E, x1.w * LOG2E);
        int chunk = (kc >> 3) ^ (r & 7);
        *reinterpret_cast<uint4*>(smem + SMEM_B + r * 512 + chunk * 16) = pk.u;
    }
}

// Group-scoped: async-copy a 32-row bf16 slice into the group's swizzled A slab.
static __device__ __forceinline__ void fill_slice(uint32_t dst,
                                                  const __nv_bfloat16* __restrict__ src,
                                                  int gtid) {
    #pragma unroll
    for (int it = 0; it < 8; it++) {
        int t = gtid + it * 128;
        int r = t >> 5;
        int c = t & 31;
        int chunk = c ^ (r & 7);
        cp_async16(dst + r * 512 + chunk * 16,
                   src + (size_t)r * NHID + c * 8);
    }
}

__global__ void __launch_bounds__(THREADS, 1)
rbm_softmax_kernel(const float* __restrict__ W, const float* __restrict__ a,
                   float* __restrict__ out) {
    extern __shared__ char smem[];
    const int tid    = threadIdx.x;
    const int lane   = tid & 31;
    const int wid    = tid >> 5;
    const int grp    = wid >> 2;      // 4 consecutive warps per group (spans SMSPs)
    const int gtid   = tid & 127;
    const int warp_n = wid & 3;
    const int cn     = warp_n * 64;
    const int n0     = blockIdx.x * TILE_N;
    const uint32_t sb = smem_u32(smem);
    const uint32_t aSlice = sb + SMEM_A + grp * (G_ROWS * 512);
    const __nv_bfloat16* hband = g_hidden + (size_t)grp * 256 * NHID;

    // Group's first A slice in flight while we convert B.
    fill_slice(aSlice, hband, gtid);
    cp_commit();

    // B tile (W slice, once per CTA): LDG f32 + cvt(*LOG2E) + STS.
    fill_B_cvt(smem, W + (size_t)n0 * NHID, tid);

    float* avec = reinterpret_cast<float*>(smem + SMEM_AVEC);
    if (tid < TILE_N) avec[tid] = a[n0 + tid] * LOG2E;

    // Folded ldmatrix bases: addr(ks) = baseX ^ ((2ks)<<4)  (rows 512B-aligned).
    const int khalf = lane >> 4;
    uint32_t aX[2];
    #pragma unroll
    for (int mi = 0; mi < 2; mi++) {
        int r = mi * 16 + (lane & 15);
        aX[mi] = (aSlice + r * 512) | ((uint32_t)((khalf ^ (r & 7)) << 4));
    }
    uint32_t bXr[4];
    #pragma unroll
    for (int p = 0; p < 4; p++) {
        int r = cn + p * 16 + (lane & 15);
        bXr[p] = (sb + SMEM_B + r * 512) | ((uint32_t)((khalf ^ (r & 7)) << 4));
    }

    cp_wait0();
    __syncthreads();   // B + all groups' slice 0 + avec visible; groups go free after this

    // One-time stagger: kick groups out of the lockstep equilibrium. The
    // staggered phase pattern is self-reinforcing afterwards (a group alone in
    // its epilogue/mainloop runs faster than when phase-sharing).
    if (grp > 0) {
        unsigned long long t0 = clock64();
        while (clock64() - t0 < STAGGER_CYC * (unsigned long long)grp) {}
    }

    // Hoisted (pre-scaled) bias values for this thread's accumulator columns.
    float av[8][2];
    #pragma unroll
    for (int ni = 0; ni < 8; ni++) {
        int c = cn + ni * 8 + 2 * (lane & 3);
        av[ni][0] = avec[c];
        av[ni][1] = avec[c + 1];
    }

    for (int sub = 0; sub < G_TILES; sub++) {
        float acc[2][8][4];
        #pragma unroll
        for (int mi = 0; mi < 2; mi++)
            #pragma unroll
            for (int ni = 0; ni < 8; ni++)
                #pragma unroll
                for (int j = 0; j < 4; j++) acc[mi][ni][j] = 0.f;

        #pragma unroll 4
        for (int ks = 0; ks < 16; ks++) {
            const uint32_t kx = (uint32_t)((2 * ks) << 4);
            uint32_t af[2][4];
            #pragma unroll
            for (int mi = 0; mi < 2; mi++)
                ldmat4(af[mi], aX[mi] ^ kx);
            uint32_t bf[8][2];
            #pragma unroll
            for (int p = 0; p < 4; p++) {
                uint32_t r4[4];
                ldmat4(r4, bXr[p] ^ kx);
                bf[2 * p][0]     = r4[0];
                bf[2 * p][1]     = r4[2];
                bf[2 * p + 1][0] = r4[1];
                bf[2 * p + 1][1] = r4[3];
            }
            #pragma unroll
            for (int mi = 0; mi < 2; mi++)
                #pragma unroll
                for (int ni = 0; ni < 8; ni++)
                    mma_bf16(acc[mi][ni], af[mi], bf[ni]);
        }
        gbar(1 + grp);     // group done reading its A slice

        // Refill group's A slice for next sub-tile; hides under the epilogue.
        if (sub + 1 < G_TILES) {
            fill_slice(aSlice, hband + (size_t)(sub + 1) * G_ROWS * NHID, gtid);
            cp_commit();
        }

        // Epilogue: per 16-col group, softmax across the 4-lane quad.
        // Logits pre-scaled by log2e -> plain ex2; tiny |logit|: no max-sub.
        const size_t rbase = (size_t)grp * 256 + (size_t)sub * G_ROWS + (lane >> 2);
        const int    cb    = n0 + cn + 2 * (lane & 3);
        #pragma unroll
        for (int mi = 0; mi < 2; mi++) {
            #pragma unroll
            for (int g = 0; g < 4; g++) {
                float e[8];
                e[0] = ex2f(acc[mi][2 * g][0]     + av[2 * g][0]);
                e[1] = ex2f(acc[mi][2 * g][1]     + av[2 * g][1]);
                e[2] = ex2f(acc[mi][2 * g + 1][0] + av[2 * g + 1][0]);
                e[3] = ex2f(acc[mi][2 * g + 1][1] + av[2 * g + 1][1]);
                e[4] = ex2f(acc[mi][2 * g][2]     + av[2 * g][0]);
                e[5] = ex2f(acc[mi][2 * g][3]     + av[2 * g][1]);
                e[6] = ex2f(acc[mi][2 * g + 1][2] + av[2 * g + 1][0]);
                e[7] = ex2f(acc[mi][2 * g + 1][3] + av[2 * g + 1][1]);

                float sA = (e[0] + e[1]) + (e[2] + e[3]);
                float sB = (e[4] + e[5]) + (e[6] + e[7]);
                sA += __shfl_xor_sync(0xffffffffu, sA, 1);
                sB += __shfl_xor_sync(0xffffffffu, sB, 1);
                sA += __shfl_xor_sync(0xffffffffu, sA, 2);
                sB += __shfl_xor_sync(0xffffffffu, sB, 2);
                float iA = __fdividef(1.0f, sA);
                float iB = __fdividef(1.0f, sB);

                size_t row = rbase + (size_t)mi * 16;
                float* o0 = out + row * NVIS + cb + 16 * g;
                *reinterpret_cast<float2*>(o0)     = make_float2(e[0] * iA, e[1] * iA);
                *reinterpret_cast<float2*>(o0 + 8) = make_float2(e[2] * iA, e[3] * iA);
                float* o1 = o0 + (size_t)8 * NVIS;
                *reinterpret_cast<float2*>(o1)     = make_float2(e[4] * iB, e[5] * iB);
                *reinterpret_cast<float2*>(o1 + 8) = make_float2(e[6] * iB, e[7] * iB);
            }
        }

        cp_wait0();
        gbar(1 + grp);     // group's next A slice resident
    }
}

extern "C" void kernel_launch(void* const* d_in, const int* in_sizes, int n_in,
                              void* d_out, int out_size) {
    const float* hidden = (const float*)d_in[0];
    const float* W      = (const float*)d_in[1];
    const float* a      = (const float*)d_in[2];
    float* out          = (float*)d_out;

    convert_hidden<<<(POP * NHID / 8 + 255) / 256, 256>>>(hidden);

    cudaFuncSetAttribute(rbm_softmax_kernel,
                         cudaFuncAttributeMaxDynamicSharedMemorySize, SMEM_TOTAL);
    rbm_softmax_kernel<<<NVIS / TILE_N, THREADS, SMEM_TOTAL>>>(W, a, out);
}